// round 12
// baseline (speedup 1.0000x reference)
#include <cuda_runtime.h>
#include <cuda_bf16.h>
#include <math.h>
#include <stdint.h>

#define NHEADS 12
#define HD 64
#define DMODEL 768
#define BATCH 4
#define SEQ 2048
#define MTOT (BATCH * SEQ)
#define KGEMM DMODEL            // 768 (direct tf32, no split)

// ---------------- device scratch (allocation-free rule) ----------------
__device__ float g_q[(size_t)BATCH * NHEADS * SEQ * HD];   // [b,h,n,d] (pre-scaled, tf32)
__device__ float g_k[(size_t)BATCH * NHEADS * SEQ * HD];   // [b,h,n,d] (tf32)
__device__ float g_v[(size_t)BATCH * NHEADS * SEQ * HD];   // [b,h,d,n] TRANSPOSED (tf32)
__device__ float g_x32[(size_t)MTOT * DMODEL];             // tf32-rounded X
__device__ float g_ctx[(size_t)MTOT * DMODEL];             // tf32-rounded ctx
__device__ float g_wt[(size_t)(3 * DMODEL) * DMODEL];      // Wqkv^T [2304][768] tf32
__device__ float g_wot[(size_t)DMODEL * DMODEL];           // Wo^T   [768][768]  tf32

// ---------------- PTX helpers ----------------
__device__ __forceinline__ uint32_t smem_u32(const void* p) {
    uint32_t a;
    asm("{ .reg .u64 t; cvta.to.shared.u64 t, %1; cvt.u32.u64 %0, t; }"
        : "=r"(a) : "l"(p));
    return a;
}
#define CPA16(dst, src) \
    asm volatile("cp.async.cg.shared.global [%0], [%1], 16;" :: "r"(dst), "l"(src))
#define CPA_COMMIT() asm volatile("cp.async.commit_group;" ::: "memory")

__device__ __forceinline__ void ldsm4(uint32_t* r, uint32_t addr) {
    asm volatile("ldmatrix.sync.aligned.m8n8.x4.shared.b16 {%0,%1,%2,%3}, [%4];"
                 : "=r"(r[0]), "=r"(r[1]), "=r"(r[2]), "=r"(r[3]) : "r"(addr));
}
__device__ __forceinline__ void mma_tf32(float* d, const uint32_t* a,
                                         const uint32_t* b) {
    asm volatile(
        "mma.sync.aligned.m16n8k8.row.col.f32.tf32.tf32.f32 "
        "{%0,%1,%2,%3}, {%4,%5,%6,%7}, {%8,%9}, {%0,%1,%2,%3};"
        : "+f"(d[0]), "+f"(d[1]), "+f"(d[2]), "+f"(d[3])
        : "r"(a[0]), "r"(a[1]), "r"(a[2]), "r"(a[3]), "r"(b[0]), "r"(b[1]));
}
// round-to-nearest tf32 (removes truncation bias of raw-f32 mma operands)
__device__ __forceinline__ float tf32r(float x) {
    float y;
    asm("cvt.rna.tf32.f32 %0, %1;" : "=f"(y) : "f"(x));
    return y;
}
// 256B-row swizzle: 16B segment XOR low 4 row bits (within 16 segs)
__device__ __forceinline__ uint32_t swz256(int row, int seg) {
    return (uint32_t)(row * 256 + (((seg ^ row) & 15) << 4) + ((seg & ~15) << 4));
}

// ---------------- conversions ----------------
// Round X to tf32 (elementwise, float4)
__global__ __launch_bounds__(256) void conv_x_kernel(
    const float* __restrict__ src, float* __restrict__ dst)
{
    int idx = blockIdx.x * 256 + threadIdx.x;
    if (idx >= MTOT * DMODEL / 4) return;
    float4 v = ((const float4*)src)[idx];
    v.x = tf32r(v.x); v.y = tf32r(v.y); v.z = tf32r(v.z); v.w = tf32r(v.w);
    ((float4*)dst)[idx] = v;
}

// Transpose W[k][n] -> Wt[n][k], rounded to tf32. z selects Wq/Wk/Wv/Wo.
__global__ __launch_bounds__(256) void conv_w_kernel(
    const float* __restrict__ Wq, const float* __restrict__ Wk,
    const float* __restrict__ Wv, const float* __restrict__ Wo)
{
    const int z = blockIdx.z;
    const float* W = (z == 0) ? Wq : (z == 1) ? Wk : (z == 2) ? Wv : Wo;
    float* dst = (z == 3) ? g_wot : g_wt;
    const int nofs = (z == 3) ? 0 : z * DMODEL;

    __shared__ float t[32][33];
    int tx = threadIdx.x & 31, ty = threadIdx.x >> 5;
    int k0 = blockIdx.y * 32, n0 = blockIdx.x * 32;
#pragma unroll
    for (int yy = ty; yy < 32; yy += 8)
        t[yy][tx] = W[(size_t)(k0 + yy) * DMODEL + n0 + tx];
    __syncthreads();
#pragma unroll
    for (int yy = ty; yy < 32; yy += 8) {
        int n = n0 + yy, k = k0 + tx;
        dst[(size_t)(nofs + n) * KGEMM + k] = tf32r(t[tx][yy]);
    }
}

// ---------------- tf32 mma.sync GEMM ----------------
// C[128x128] = A[row0:+128, :768] x B[col0:+128, :768]^T, k-chunk 64, 2-stage.
// 8 warps (4 M x 2 N), warp tile 32x64. Fragment layout mirrors attention.
// mode 0: scatter q (x0.125) / k / v(transposed), all tf32-rounded.
// mode 1: Out = C + bias (final f32, no rounding).
#define NKCH (KGEMM / 64)       // 12
#define GEMM_SMEM (2 * 65536)   // per stage: A 32K + B 32K

__global__ __launch_bounds__(256) void mma_gemm_kernel(
    const float* __restrict__ A,
    const float* __restrict__ B,
    const float* __restrict__ bias,
    float* __restrict__ OutF, int mode)
{
    extern __shared__ char smem[];
    const uint32_t sb = smem_u32(smem);
    const int tid = threadIdx.x, wid = tid >> 5, lid = tid & 31;
    const int row0 = blockIdx.y * 128, col0 = blockIdx.x * 128;
    const int m0 = (wid & 3) * 32, n0 = (wid >> 2) * 64;

    const float* Ab = A + (size_t)row0 * KGEMM;
    const float* Bb = B + (size_t)col0 * KGEMM;

    float acc[2][8][4];
#pragma unroll
    for (int mf = 0; mf < 2; mf++)
#pragma unroll
        for (int nf = 0; nf < 8; nf++)
#pragma unroll
            for (int e = 0; e < 4; e++) acc[mf][nf][e] = 0.f;

    auto load_chunk = [&](int i, int bf) {
        const uint32_t bA = sb + bf * 65536;
        const uint32_t bB = bA + 32768;
        const int kofs = i * 64;
#pragma unroll
        for (int c = 0; c < 8; c++) {
            const int idx = tid + c * 256, row = idx >> 4, sg = idx & 15;
            const uint32_t sw = swz256(row, sg);
            CPA16(bA + sw, Ab + (size_t)row * KGEMM + kofs + sg * 4);
            CPA16(bB + sw, Bb + (size_t)row * KGEMM + kofs + sg * 4);
        }
        CPA_COMMIT();
    };

    const int asoff = lid >> 4;          // A: 16 rows x (lid>>4) seg half
    const int arow = lid & 15;
    const int brow = lid & 7, bsoff = lid >> 3;

    load_chunk(0, 0);
    for (int i = 0; i < NKCH; i++) {
        if (i + 1 < NKCH) {
            load_chunk(i + 1, (i + 1) & 1);
            asm volatile("cp.async.wait_group 1;" ::: "memory");
        } else {
            asm volatile("cp.async.wait_group 0;" ::: "memory");
        }
        __syncthreads();

        const uint32_t bufA = sb + (i & 1) * 65536;
        const uint32_t bufB = bufA + 32768;
#pragma unroll
        for (int ks = 0; ks < 4; ks++) {   // k16 steps within chunk
            uint32_t a[2][2][4];           // [mf][k8 half]
#pragma unroll
            for (int mf = 0; mf < 2; mf++) {
                const int rA = m0 + mf * 16 + arow;
                ldsm4(a[mf][0], bufA + swz256(rA, ks * 4 + asoff));
                ldsm4(a[mf][1], bufA + swz256(rA, ks * 4 + 2 + asoff));
            }
#pragma unroll
            for (int nf = 0; nf < 8; nf++) {
                uint32_t b4[4];
                ldsm4(b4, bufB + swz256(n0 + nf * 8 + brow, ks * 4 + bsoff));
#pragma unroll
                for (int mf = 0; mf < 2; mf++) {
                    mma_tf32(acc[mf][nf], a[mf][0], b4);
                    mma_tf32(acc[mf][nf], a[mf][1], b4 + 2);
                }
            }
        }
        __syncthreads();
    }

    const int g = lid >> 2, tig = lid & 3;
#pragma unroll
    for (int mf = 0; mf < 2; mf++) {
#pragma unroll
        for (int nf = 0; nf < 8; nf++) {
            const int c = col0 + n0 + nf * 8 + tig * 2;
#pragma unroll
            for (int rr = 0; rr < 2; rr++) {
                const int r = row0 + m0 + mf * 16 + g + rr * 8;
                const float v0 = acc[mf][nf][rr * 2 + 0];
                const float v1 = acc[mf][nf][rr * 2 + 1];
                if (mode == 0) {
                    const int w = c / DMODEL;
                    const int rem = c - w * DMODEL;
                    const int h = rem >> 6, d = rem & 63;
                    const int bb = r >> 11, n = r & (SEQ - 1);
                    if (w == 0) {        // Q: pre-scale 1/8, round to tf32
                        float2* p = (float2*)(g_q +
                            ((size_t)(bb * NHEADS + h) * SEQ + n) * HD + d);
                        *p = make_float2(tf32r(v0 * 0.125f), tf32r(v1 * 0.125f));
                    } else if (w == 1) { // K: tf32-rounded
                        float2* p = (float2*)(g_k +
                            ((size_t)(bb * NHEADS + h) * SEQ + n) * HD + d);
                        *p = make_float2(tf32r(v0), tf32r(v1));
                    } else {             // V: TRANSPOSED [b,h,d,n], tf32-rounded
                        float* p = g_v +
                            ((size_t)(bb * NHEADS + h) * HD + d) * SEQ + n;
                        p[0] = tf32r(v0);
                        p[SEQ] = tf32r(v1);
                    }
                } else {                 // final output: f32 + bias
                    float2* p = (float2*)(OutF + (size_t)r * DMODEL + c);
                    *p = make_float2(v0 + bias[c], v1 + bias[c + 1]);
                }
            }
        }
    }
}

// ---------------------------------------------------------------------------
// Tensor-core flash attention (tf32 mma.sync, causal, no running max).
// R9 configuration: QUADRANT mapping, K/V double-buffered, 128 thr / 64 q-rows.
// Inputs are tf32-rounded -> mma products exact; P rounded before PV.
// ---------------------------------------------------------------------------
#define ATT_SMEM (98304 + 512)

__global__ __launch_bounds__(128) void attn_mma_kernel()
{
    extern __shared__ char smc[];
    const uint32_t sb = smem_u32(smc);
    const uint32_t Qs = sb;              // [64][64] f32 swizzled  16KB
    const uint32_t Kb = sb + 16384;      // 2 x [64][64]           32KB
    const uint32_t Vb = sb + 49152;      // 2 x [64][64] (Vt)      32KB
    const uint32_t Pb = sb + 81920;      // [64][64]               16KB
    float* larr = (float*)(smc + 98304); // [2][64] l partials

    const int tid = threadIdx.x, w = tid >> 5, lid = tid & 31;
    const int g = lid >> 2, tig = lid & 3;
    const int rq = (w & 1) * 32;         // q-row quadrant base
    const int ck = (w >> 1) * 32;        // k/V-col quadrant base
    const int qt = (int)gridDim.x - 1 - (int)blockIdx.x;   // heavy first
    const int bh = blockIdx.y;
    const int q0 = qt * 64;
    const int nk = qt + 1;

    const float* qb = g_q + (size_t)bh * SEQ * HD;
    const float* kb = g_k + (size_t)bh * SEQ * HD;
    const float* vtb = g_v + (size_t)bh * HD * SEQ;   // [d][n]

    // ---- Q tile ----
#pragma unroll
    for (int c = 0; c < 8; c++) {
        const int idx = tid + c * 128, row = idx >> 4, seg = idx & 15;
        CPA16(Qs + swz256(row, seg), qb + (size_t)(q0 + row) * HD + seg * 4);
    }
    auto load_kv = [&](int i, int bf) {
        const int k0 = i * 64;
        const uint32_t kd = Kb + bf * 16384, vd = Vb + bf * 16384;
#pragma unroll
        for (int c = 0; c < 8; c++) {
            const int idx = tid + c * 128, row = idx >> 4, seg = idx & 15;
            const uint32_t sw = swz256(row, seg);
            CPA16(kd + sw, kb + (size_t)(k0 + row) * HD + seg * 4);
            CPA16(vd + sw, vtb + (size_t)row * SEQ + k0 + seg * 4);
        }
        CPA_COMMIT();
    };
    load_kv(0, 0);
    if (nk > 1) load_kv(1, 1);
    if (nk > 1) asm volatile("cp.async.wait_group 1;" ::: "memory");
    else        asm volatile("cp.async.wait_group 0;" ::: "memory");
    __syncthreads();

    // ---- Q fragments (32 rows = 2 m16 frags x 8 k-steps, in registers) ----
    const int asoff = lid >> 4;
    uint32_t qf[2][8][4];
#pragma unroll
    for (int mf = 0; mf < 2; mf++) {
        const int rowQ = rq + mf * 16 + (lid & 15);
#pragma unroll
        for (int kk = 0; kk < 8; kk++)
            ldsm4(qf[mf][kk], Qs + swz256(rowQ, kk * 2 + asoff));
    }

    const int brow = lid & 7, bsoff = lid >> 3;

    float oacc[2][4][4];
#pragma unroll
    for (int mf = 0; mf < 2; mf++)
#pragma unroll
        for (int nf = 0; nf < 4; nf++)
#pragma unroll
            for (int e = 0; e < 4; e++) oacc[mf][nf][e] = 0.f;
    float lsum[2][2] = {{0.f, 0.f}, {0.f, 0.f}};

    for (int i = 0; i < nk; i++) {
        const uint32_t Kc = Kb + (i & 1) * 16384;
        const uint32_t Vc = Vb + (i & 1) * 16384;

        // ---- S quadrant = Q[rq:+32] K[ck:+32]^T ----
        float sacc[2][4][4];
#pragma unroll
        for (int mf = 0; mf < 2; mf++)
#pragma unroll
            for (int nf = 0; nf < 4; nf++)
#pragma unroll
                for (int e = 0; e < 4; e++) sacc[mf][nf][e] = 0.f;
#pragma unroll
        for (int nf = 0; nf < 4; nf++) {
            const int krow = ck + nf * 8 + brow;
#pragma unroll
            for (int k2 = 0; k2 < 4; k2++) {
                uint32_t b[4];
                ldsm4(b, Kc + swz256(krow, k2 * 4 + bsoff));
#pragma unroll
                for (int mf = 0; mf < 2; mf++) {
                    mma_tf32(sacc[mf][nf], qf[mf][2 * k2], b);
                    mma_tf32(sacc[mf][nf], qf[mf][2 * k2 + 1], b + 2);
                }
            }
        }

        // ---- causal mask (diagonal tile only) ----
        const int k0 = i * 64;
        if (i == qt) {
#pragma unroll
            for (int mf = 0; mf < 2; mf++) {
                const int rA = q0 + rq + mf * 16 + g;
                const int rB = rA + 8;
#pragma unroll
                for (int nf = 0; nf < 4; nf++) {
                    const int c0 = k0 + ck + nf * 8 + 2 * tig;
                    if (c0 > rA) sacc[mf][nf][0] = -INFINITY;
                    if (c0 + 1 > rA) sacc[mf][nf][1] = -INFINITY;
                    if (c0 > rB) sacc[mf][nf][2] = -INFINITY;
                    if (c0 + 1 > rB) sacc[mf][nf][3] = -INFINITY;
                }
            }
        }

        // ---- P = tf32(exp(S)), accumulate l, store quadrant to shared P ----
#pragma unroll
        for (int mf = 0; mf < 2; mf++) {
            const int prowA = rq + mf * 16 + g;
            const int prowB = prowA + 8;
#pragma unroll
            for (int nf = 0; nf < 4; nf++) {
                const float p0 = tf32r(__expf(sacc[mf][nf][0]));
                const float p1 = tf32r(__expf(sacc[mf][nf][1]));
                const float p2 = tf32r(__expf(sacc[mf][nf][2]));
                const float p3 = tf32r(__expf(sacc[mf][nf][3]));
                lsum[mf][0] += p0 + p1;
                lsum[mf][1] += p2 + p3;
                const int col = ck + nf * 8 + 2 * tig;
                const int segp = col >> 2, off = (col & 3) * 4;
                asm volatile("st.shared.v2.f32 [%0], {%1,%2};"
                             :: "r"(Pb + swz256(prowA, segp) + off),
                                "f"(p0), "f"(p1) : "memory");
                asm volatile("st.shared.v2.f32 [%0], {%1,%2};"
                             :: "r"(Pb + swz256(prowB, segp) + off),
                                "f"(p2), "f"(p3) : "memory");
            }
        }
        __syncthreads();   // all warps' P quadrants visible

        // ---- O quadrant += P[rq:+32, :] V[:, ck:+32] ----
#pragma unroll
        for (int k2 = 0; k2 < 4; k2++) {
            uint32_t pa[2][2][4];
#pragma unroll
            for (int mf = 0; mf < 2; mf++) {
                const int prow = rq + mf * 16 + (lid & 15);
                ldsm4(pa[mf][0], Pb + swz256(prow, (2 * k2) * 2 + asoff));
                ldsm4(pa[mf][1], Pb + swz256(prow, (2 * k2 + 1) * 2 + asoff));
            }
#pragma unroll
            for (int nf = 0; nf < 4; nf++) {
                uint32_t vb4[4];
                ldsm4(vb4, Vc + swz256(ck + nf * 8 + brow, k2 * 4 + bsoff));
#pragma unroll
                for (int mf = 0; mf < 2; mf++) {
                    mma_tf32(oacc[mf][nf], pa[mf][0], vb4);
                    mma_tf32(oacc[mf][nf], pa[mf][1], vb4 + 2);
                }
            }
        }

        __syncthreads();                 // PV reads done (P + K/V bufs free)
        if (i + 2 < nk) load_kv(i + 2, i & 1);
        if (i + 1 < nk) {
            if (i + 2 < nk)
                asm volatile("cp.async.wait_group 1;" ::: "memory");
            else
                asm volatile("cp.async.wait_group 0;" ::: "memory");
            __syncthreads();
        }
    }

    // ---- l: quad-reduce then cross-warp (col halves) combine via smem ----
#pragma unroll
    for (int mf = 0; mf < 2; mf++)
#pragma unroll
        for (int rr = 0; rr < 2; rr++) {
            lsum[mf][rr] += __shfl_xor_sync(0xffffffff, lsum[mf][rr], 1);
            lsum[mf][rr] += __shfl_xor_sync(0xffffffff, lsum[mf][rr], 2);
        }
    if (tig == 0) {
#pragma unroll
        for (int mf = 0; mf < 2; mf++)
#pragma unroll
            for (int rr = 0; rr < 2; rr++)
                larr[(w >> 1) * 64 + rq + mf * 16 + g + rr * 8] = lsum[mf][rr];
    }
    __syncthreads();

    // ---- epilogue: normalize + write tf32-rounded f32 ctx ----
    const int bb = bh / NHEADS, h = bh - bb * NHEADS;
#pragma unroll
    for (int mf = 0; mf < 2; mf++) {
#pragma unroll
        for (int rr = 0; rr < 2; rr++) {
            const int rl = rq + mf * 16 + g + rr * 8;
            const float inv = 1.f / (larr[rl] + larr[64 + rl]);
            const int r = q0 + rl;
#pragma unroll
            for (int nf = 0; nf < 4; nf++) {
                const int c = ck + nf * 8 + 2 * tig;
                const float v0 = oacc[mf][nf][rr * 2 + 0] * inv;
                const float v1 = oacc[mf][nf][rr * 2 + 1] * inv;
                float2* p = (float2*)(g_ctx +
                    (size_t)(bb * SEQ + r) * DMODEL + h * HD + c);
                *p = make_float2(tf32r(v0), tf32r(v1));
            }
        }
    }
}

// ---------------------------------------------------------------------------
extern "C" void kernel_launch(void* const* d_in, const int* in_sizes, int n_in,
                              void* d_out, int out_size)
{
    const float* X  = (const float*)d_in[0];
    const float* Wq = (const float*)d_in[1];
    const float* Wk = (const float*)d_in[2];
    const float* Wv = (const float*)d_in[3];
    const float* Wo = (const float*)d_in[4];
    const float* bo = (const float*)d_in[5];
    float* Out = (float*)d_out;

    cudaFuncSetAttribute(mma_gemm_kernel,
                         cudaFuncAttributeMaxDynamicSharedMemorySize, GEMM_SMEM);
    cudaFuncSetAttribute(attn_mma_kernel,
                         cudaFuncAttributeMaxDynamicSharedMemorySize, ATT_SMEM);

    float *x32_p, *ctx_p, *wt_p, *wot_p;
    cudaGetSymbolAddress((void**)&x32_p, g_x32);
    cudaGetSymbolAddress((void**)&ctx_p, g_ctx);
    cudaGetSymbolAddress((void**)&wt_p, g_wt);
    cudaGetSymbolAddress((void**)&wot_p, g_wot);

    conv_x_kernel<<<(MTOT * DMODEL / 4 + 255) / 256, 256>>>(X, x32_p);
    dim3 wgrid(DMODEL / 32, DMODEL / 32, 4);
    conv_w_kernel<<<wgrid, 256>>>(Wq, Wk, Wv, Wo);

    // fused QKV projection: [8192 x 2304] = X @ Wqkv^T (tf32)
    dim3 g1(3 * DMODEL / 128, MTOT / 128);
    mma_gemm_kernel<<<g1, 256, GEMM_SMEM>>>(x32_p, wt_p, nullptr, nullptr, 0);

    dim3 g2(SEQ / 64, BATCH * NHEADS);
    attn_mma_kernel<<<g2, 128, ATT_SMEM>>>();

    // output projection: [8192 x 768] = ctx @ Wo^T + bo (tf32)
    dim3 g3(DMODEL / 128, MTOT / 128);
    mma_gemm_kernel<<<g3, 256, GEMM_SMEM>>>(ctx_p, wot_p, bo, Out, 1);
}

// round 13
// speedup vs baseline: 1.4607x; 1.4607x over previous
#include <cuda_runtime.h>
#include <cuda_bf16.h>
#include <math.h>
#include <stdint.h>

#define NHEADS 12
#define HD 64
#define DMODEL 768
#define BATCH 4
#define SEQ 2048
#define MTOT (BATCH * SEQ)
#define KGEMM DMODEL            // 768 (direct tf32, no split)

// ---------------- device scratch (allocation-free rule) ----------------
__device__ float g_q[(size_t)BATCH * NHEADS * SEQ * HD];   // [b,h,n,d] (pre-scaled, tf32)
__device__ float g_k[(size_t)BATCH * NHEADS * SEQ * HD];   // [b,h,n,d] (tf32)
__device__ float g_v[(size_t)BATCH * NHEADS * SEQ * HD];   // [b,h,d,n] TRANSPOSED (tf32)
__device__ float g_x32[(size_t)MTOT * DMODEL];             // tf32-rounded X
__device__ float g_ctx[(size_t)MTOT * DMODEL];             // ctx (f32)
__device__ float g_wt[(size_t)(3 * DMODEL) * DMODEL];      // Wqkv^T [2304][768] tf32
__device__ float g_wot[(size_t)DMODEL * DMODEL];           // Wo^T   [768][768]  tf32

// ---------------- PTX helpers ----------------
__device__ __forceinline__ uint32_t smem_u32(const void* p) {
    uint32_t a;
    asm("{ .reg .u64 t; cvta.to.shared.u64 t, %1; cvt.u32.u64 %0, t; }"
        : "=r"(a) : "l"(p));
    return a;
}
#define CPA16(dst, src) \
    asm volatile("cp.async.cg.shared.global [%0], [%1], 16;" :: "r"(dst), "l"(src))
#define CPA_COMMIT() asm volatile("cp.async.commit_group;" ::: "memory")

__device__ __forceinline__ void ldsm4(uint32_t* r, uint32_t addr) {
    asm volatile("ldmatrix.sync.aligned.m8n8.x4.shared.b16 {%0,%1,%2,%3}, [%4];"
                 : "=r"(r[0]), "=r"(r[1]), "=r"(r[2]), "=r"(r[3]) : "r"(addr));
}
__device__ __forceinline__ void mma_tf32(float* d, const uint32_t* a,
                                         const uint32_t* b) {
    asm volatile(
        "mma.sync.aligned.m16n8k8.row.col.f32.tf32.tf32.f32 "
        "{%0,%1,%2,%3}, {%4,%5,%6,%7}, {%8,%9}, {%0,%1,%2,%3};"
        : "+f"(d[0]), "+f"(d[1]), "+f"(d[2]), "+f"(d[3])
        : "r"(a[0]), "r"(a[1]), "r"(a[2]), "r"(a[3]), "r"(b[0]), "r"(b[1]));
}
// round-to-nearest tf32. EXPENSIVE (ptxas emits an integer sequence) —
// use only in prep kernels / epilogues, NEVER in hot loops.
__device__ __forceinline__ float tf32r(float x) {
    float y;
    asm("cvt.rna.tf32.f32 %0, %1;" : "=f"(y) : "f"(x));
    return y;
}
// 256B-row swizzle (attention tiles): 16B seg XOR low 4 row bits
__device__ __forceinline__ uint32_t swz256(int row, int seg) {
    return (uint32_t)(row * 256 + (((seg ^ row) & 15) << 4) + ((seg & ~15) << 4));
}
// 128B-row swizzle (GEMM tiles): 16B seg XOR low 3 row bits
__device__ __forceinline__ uint32_t swz128(int row, int seg) {
    return (uint32_t)(row * 128 + (((seg ^ row) & 7) << 4));
}

// ---------------- conversions ----------------
__global__ __launch_bounds__(256) void conv_x_kernel(
    const float* __restrict__ src, float* __restrict__ dst)
{
    int idx = blockIdx.x * 256 + threadIdx.x;
    if (idx >= MTOT * DMODEL / 4) return;
    float4 v = ((const float4*)src)[idx];
    v.x = tf32r(v.x); v.y = tf32r(v.y); v.z = tf32r(v.z); v.w = tf32r(v.w);
    ((float4*)dst)[idx] = v;
}

// Transpose W[k][n] -> Wt[n][k], rounded to tf32. z selects Wq/Wk/Wv/Wo.
__global__ __launch_bounds__(256) void conv_w_kernel(
    const float* __restrict__ Wq, const float* __restrict__ Wk,
    const float* __restrict__ Wv, const float* __restrict__ Wo)
{
    const int z = blockIdx.z;
    const float* W = (z == 0) ? Wq : (z == 1) ? Wk : (z == 2) ? Wv : Wo;
    float* dst = (z == 3) ? g_wot : g_wt;
    const int nofs = (z == 3) ? 0 : z * DMODEL;

    __shared__ float t[32][33];
    int tx = threadIdx.x & 31, ty = threadIdx.x >> 5;
    int k0 = blockIdx.y * 32, n0 = blockIdx.x * 32;
#pragma unroll
    for (int yy = ty; yy < 32; yy += 8)
        t[yy][tx] = W[(size_t)(k0 + yy) * DMODEL + n0 + tx];
    __syncthreads();
#pragma unroll
    for (int yy = ty; yy < 32; yy += 8) {
        int n = n0 + yy, k = k0 + tx;
        dst[(size_t)(nofs + n) * KGEMM + k] = tf32r(t[tx][yy]);
    }
}

// ---------------- tf32 mma.sync GEMM (k-chunk 32, 64KB smem) ----------------
// C[128x128] = A[row0:+128, :768] x B[col0:+128, :768]^T
// 8 warps (4 M x 2 N), warp tile 32x64, 2-stage cp.async.
// mode 0: scatter q (x0.125) / k / v(transposed), tf32-rounded (epilogue-only).
// mode 1: Out = C + bias.
#define NKCH (KGEMM / 32)       // 24
#define GEMM_SMEM (2 * 32768)   // per stage: A 16K + B 16K

__global__ __launch_bounds__(256) void mma_gemm_kernel(
    const float* __restrict__ A,
    const float* __restrict__ B,
    const float* __restrict__ bias,
    float* __restrict__ OutF, int mode)
{
    extern __shared__ char smem[];
    const uint32_t sb = smem_u32(smem);
    const int tid = threadIdx.x, wid = tid >> 5, lid = tid & 31;
    const int row0 = blockIdx.y * 128, col0 = blockIdx.x * 128;
    const int m0 = (wid & 3) * 32, n0 = (wid >> 2) * 64;

    const float* Ab = A + (size_t)row0 * KGEMM;
    const float* Bb = B + (size_t)col0 * KGEMM;

    float acc[2][8][4];
#pragma unroll
    for (int mf = 0; mf < 2; mf++)
#pragma unroll
        for (int nf = 0; nf < 8; nf++)
#pragma unroll
            for (int e = 0; e < 4; e++) acc[mf][nf][e] = 0.f;

    auto load_chunk = [&](int i, int bf) {
        const uint32_t bA = sb + bf * 32768;
        const uint32_t bB = bA + 16384;
        const int kofs = i * 32;
#pragma unroll
        for (int c = 0; c < 4; c++) {
            const int idx = tid + c * 256, row = idx >> 3, sg = idx & 7;
            const uint32_t sw = swz128(row, sg);
            CPA16(bA + sw, Ab + (size_t)row * KGEMM + kofs + sg * 4);
            CPA16(bB + sw, Bb + (size_t)row * KGEMM + kofs + sg * 4);
        }
        CPA_COMMIT();
    };

    const int asoff = lid >> 4;          // 0/1
    const int arow = lid & 15;
    const int brow = lid & 7, bsoff = lid >> 3;   // 0..3

    load_chunk(0, 0);
    for (int i = 0; i < NKCH; i++) {
        if (i + 1 < NKCH) {
            load_chunk(i + 1, (i + 1) & 1);
            asm volatile("cp.async.wait_group 1;" ::: "memory");
        } else {
            asm volatile("cp.async.wait_group 0;" ::: "memory");
        }
        __syncthreads();

        const uint32_t bufA = sb + (i & 1) * 32768;
        const uint32_t bufB = bufA + 16384;
#pragma unroll
        for (int ks = 0; ks < 2; ks++) {   // two k16 steps per 32-chunk
            uint32_t a[2][2][4];           // [mf][k8 half]
#pragma unroll
            for (int mf = 0; mf < 2; mf++) {
                const int rA = m0 + mf * 16 + arow;
                ldsm4(a[mf][0], bufA + swz128(rA, ks * 4 + asoff));
                ldsm4(a[mf][1], bufA + swz128(rA, ks * 4 + 2 + asoff));
            }
#pragma unroll
            for (int nf = 0; nf < 8; nf++) {
                uint32_t b4[4];
                ldsm4(b4, bufB + swz128(n0 + nf * 8 + brow, ks * 4 + bsoff));
#pragma unroll
                for (int mf = 0; mf < 2; mf++) {
                    mma_tf32(acc[mf][nf], a[mf][0], b4);
                    mma_tf32(acc[mf][nf], a[mf][1], b4 + 2);
                }
            }
        }
        __syncthreads();
    }

    const int g = lid >> 2, tig = lid & 3;
#pragma unroll
    for (int mf = 0; mf < 2; mf++) {
#pragma unroll
        for (int nf = 0; nf < 8; nf++) {
            const int c = col0 + n0 + nf * 8 + tig * 2;
#pragma unroll
            for (int rr = 0; rr < 2; rr++) {
                const int r = row0 + m0 + mf * 16 + g + rr * 8;
                const float v0 = acc[mf][nf][rr * 2 + 0];
                const float v1 = acc[mf][nf][rr * 2 + 1];
                if (mode == 0) {
                    const int w = c / DMODEL;
                    const int rem = c - w * DMODEL;
                    const int h = rem >> 6, d = rem & 63;
                    const int bb = r >> 11, n = r & (SEQ - 1);
                    if (w == 0) {        // Q: pre-scale 1/8, round to tf32
                        float2* p = (float2*)(g_q +
                            ((size_t)(bb * NHEADS + h) * SEQ + n) * HD + d);
                        *p = make_float2(tf32r(v0 * 0.125f), tf32r(v1 * 0.125f));
                    } else if (w == 1) { // K: tf32-rounded
                        float2* p = (float2*)(g_k +
                            ((size_t)(bb * NHEADS + h) * SEQ + n) * HD + d);
                        *p = make_float2(tf32r(v0), tf32r(v1));
                    } else {             // V: TRANSPOSED [b,h,d,n], tf32-rounded
                        float* p = g_v +
                            ((size_t)(bb * NHEADS + h) * HD + d) * SEQ + n;
                        p[0] = tf32r(v0);
                        p[SEQ] = tf32r(v1);
                    }
                } else {                 // final output: f32 + bias
                    float2* p = (float2*)(OutF + (size_t)r * DMODEL + c);
                    *p = make_float2(v0 + bias[c], v1 + bias[c + 1]);
                }
            }
        }
    }
}

// ---------------------------------------------------------------------------
// Tensor-core flash attention (tf32 mma.sync, causal, no running max).
// EXACT R9 hot loop: QUADRANT mapping, K/V double-buffered, 128 thr / 64 rows.
// No tf32r anywhere inside. Epilogue writes plain f32 ctx.
// ---------------------------------------------------------------------------
#define ATT_SMEM (98304 + 512)

__global__ __launch_bounds__(128) void attn_mma_kernel()
{
    extern __shared__ char smc[];
    const uint32_t sb = smem_u32(smc);
    const uint32_t Qs = sb;              // [64][64] f32 swizzled  16KB
    const uint32_t Kb = sb + 16384;      // 2 x [64][64]           32KB
    const uint32_t Vb = sb + 49152;      // 2 x [64][64] (Vt)      32KB
    const uint32_t Pb = sb + 81920;      // [64][64]               16KB
    float* larr = (float*)(smc + 98304); // [2][64] l partials

    const int tid = threadIdx.x, w = tid >> 5, lid = tid & 31;
    const int g = lid >> 2, tig = lid & 3;
    const int rq = (w & 1) * 32;         // q-row quadrant base
    const int ck = (w >> 1) * 32;        // k/V-col quadrant base
    const int qt = (int)gridDim.x - 1 - (int)blockIdx.x;   // heavy first
    const int bh = blockIdx.y;
    const int q0 = qt * 64;
    const int nk = qt + 1;

    const float* qb = g_q + (size_t)bh * SEQ * HD;
    const float* kb = g_k + (size_t)bh * SEQ * HD;
    const float* vtb = g_v + (size_t)bh * HD * SEQ;   // [d][n]

    // ---- Q tile ----
#pragma unroll
    for (int c = 0; c < 8; c++) {
        const int idx = tid + c * 128, row = idx >> 4, seg = idx & 15;
        CPA16(Qs + swz256(row, seg), qb + (size_t)(q0 + row) * HD + seg * 4);
    }
    auto load_kv = [&](int i, int bf) {
        const int k0 = i * 64;
        const uint32_t kd = Kb + bf * 16384, vd = Vb + bf * 16384;
#pragma unroll
        for (int c = 0; c < 8; c++) {
            const int idx = tid + c * 128, row = idx >> 4, seg = idx & 15;
            const uint32_t sw = swz256(row, seg);
            CPA16(kd + sw, kb + (size_t)(k0 + row) * HD + seg * 4);
            CPA16(vd + sw, vtb + (size_t)row * SEQ + k0 + seg * 4);
        }
        CPA_COMMIT();
    };
    load_kv(0, 0);
    if (nk > 1) load_kv(1, 1);
    if (nk > 1) asm volatile("cp.async.wait_group 1;" ::: "memory");
    else        asm volatile("cp.async.wait_group 0;" ::: "memory");
    __syncthreads();

    // ---- Q fragments (32 rows = 2 m16 frags x 8 k-steps, in registers) ----
    const int asoff = lid >> 4;
    uint32_t qf[2][8][4];
#pragma unroll
    for (int mf = 0; mf < 2; mf++) {
        const int rowQ = rq + mf * 16 + (lid & 15);
#pragma unroll
        for (int kk = 0; kk < 8; kk++)
            ldsm4(qf[mf][kk], Qs + swz256(rowQ, kk * 2 + asoff));
    }

    const int brow = lid & 7, bsoff = lid >> 3;

    float oacc[2][4][4];
#pragma unroll
    for (int mf = 0; mf < 2; mf++)
#pragma unroll
        for (int nf = 0; nf < 4; nf++)
#pragma unroll
            for (int e = 0; e < 4; e++) oacc[mf][nf][e] = 0.f;
    float lsum[2][2] = {{0.f, 0.f}, {0.f, 0.f}};

    for (int i = 0; i < nk; i++) {
        const uint32_t Kc = Kb + (i & 1) * 16384;
        const uint32_t Vc = Vb + (i & 1) * 16384;

        // ---- S quadrant = Q[rq:+32] K[ck:+32]^T ----
        float sacc[2][4][4];
#pragma unroll
        for (int mf = 0; mf < 2; mf++)
#pragma unroll
            for (int nf = 0; nf < 4; nf++)
#pragma unroll
                for (int e = 0; e < 4; e++) sacc[mf][nf][e] = 0.f;
#pragma unroll
        for (int nf = 0; nf < 4; nf++) {
            const int krow = ck + nf * 8 + brow;
#pragma unroll
            for (int k2 = 0; k2 < 4; k2++) {
                uint32_t b[4];
                ldsm4(b, Kc + swz256(krow, k2 * 4 + bsoff));
#pragma unroll
                for (int mf = 0; mf < 2; mf++) {
                    mma_tf32(sacc[mf][nf], qf[mf][2 * k2], b);
                    mma_tf32(sacc[mf][nf], qf[mf][2 * k2 + 1], b + 2);
                }
            }
        }

        // ---- causal mask (diagonal tile only) ----
        const int k0 = i * 64;
        if (i == qt) {
#pragma unroll
            for (int mf = 0; mf < 2; mf++) {
                const int rA = q0 + rq + mf * 16 + g;
                const int rB = rA + 8;
#pragma unroll
                for (int nf = 0; nf < 4; nf++) {
                    const int c0 = k0 + ck + nf * 8 + 2 * tig;
                    if (c0 > rA) sacc[mf][nf][0] = -INFINITY;
                    if (c0 + 1 > rA) sacc[mf][nf][1] = -INFINITY;
                    if (c0 > rB) sacc[mf][nf][2] = -INFINITY;
                    if (c0 + 1 > rB) sacc[mf][nf][3] = -INFINITY;
                }
            }
        }

        // ---- P = exp(S), accumulate l, store quadrant to shared P ----
#pragma unroll
        for (int mf = 0; mf < 2; mf++) {
            const int prowA = rq + mf * 16 + g;
            const int prowB = prowA + 8;
#pragma unroll
            for (int nf = 0; nf < 4; nf++) {
                const float p0 = __expf(sacc[mf][nf][0]);
                const float p1 = __expf(sacc[mf][nf][1]);
                const float p2 = __expf(sacc[mf][nf][2]);
                const float p3 = __expf(sacc[mf][nf][3]);
                lsum[mf][0] += p0 + p1;
                lsum[mf][1] += p2 + p3;
                const int col = ck + nf * 8 + 2 * tig;
                const int segp = col >> 2, off = (col & 3) * 4;
                asm volatile("st.shared.v2.f32 [%0], {%1,%2};"
                             :: "r"(Pb + swz256(prowA, segp) + off),
                                "f"(p0), "f"(p1) : "memory");
                asm volatile("st.shared.v2.f32 [%0], {%1,%2};"
                             :: "r"(Pb + swz256(prowB, segp) + off),
                                "f"(p2), "f"(p3) : "memory");
            }
        }
        __syncthreads();   // all warps' P quadrants visible

        // ---- O quadrant += P[rq:+32, :] V[:, ck:+32] ----
#pragma unroll
        for (int k2 = 0; k2 < 4; k2++) {
            uint32_t pa[2][2][4];
#pragma unroll
            for (int mf = 0; mf < 2; mf++) {
                const int prow = rq + mf * 16 + (lid & 15);
                ldsm4(pa[mf][0], Pb + swz256(prow, (2 * k2) * 2 + asoff));
                ldsm4(pa[mf][1], Pb + swz256(prow, (2 * k2 + 1) * 2 + asoff));
            }
#pragma unroll
            for (int nf = 0; nf < 4; nf++) {
                uint32_t vb4[4];
                ldsm4(vb4, Vc + swz256(ck + nf * 8 + brow, k2 * 4 + bsoff));
#pragma unroll
                for (int mf = 0; mf < 2; mf++) {
                    mma_tf32(oacc[mf][nf], pa[mf][0], vb4);
                    mma_tf32(oacc[mf][nf], pa[mf][1], vb4 + 2);
                }
            }
        }

        __syncthreads();                 // PV reads done (P + K/V bufs free)
        if (i + 2 < nk) load_kv(i + 2, i & 1);
        if (i + 1 < nk) {
            if (i + 2 < nk)
                asm volatile("cp.async.wait_group 1;" ::: "memory");
            else
                asm volatile("cp.async.wait_group 0;" ::: "memory");
            __syncthreads();
        }
    }

    // ---- l: quad-reduce then cross-warp (col halves) combine via smem ----
#pragma unroll
    for (int mf = 0; mf < 2; mf++)
#pragma unroll
        for (int rr = 0; rr < 2; rr++) {
            lsum[mf][rr] += __shfl_xor_sync(0xffffffff, lsum[mf][rr], 1);
            lsum[mf][rr] += __shfl_xor_sync(0xffffffff, lsum[mf][rr], 2);
        }
    if (tig == 0) {
#pragma unroll
        for (int mf = 0; mf < 2; mf++)
#pragma unroll
            for (int rr = 0; rr < 2; rr++)
                larr[(w >> 1) * 64 + rq + mf * 16 + g + rr * 8] = lsum[mf][rr];
    }
    __syncthreads();

    // ---- epilogue: normalize + write plain f32 ctx ----
    const int bb = bh / NHEADS, h = bh - bb * NHEADS;
#pragma unroll
    for (int mf = 0; mf < 2; mf++) {
#pragma unroll
        for (int rr = 0; rr < 2; rr++) {
            const int rl = rq + mf * 16 + g + rr * 8;
            const float inv = 1.f / (larr[rl] + larr[64 + rl]);
            const int r = q0 + rl;
#pragma unroll
            for (int nf = 0; nf < 4; nf++) {
                const int c = ck + nf * 8 + 2 * tig;
                float2* p = (float2*)(g_ctx +
                    (size_t)(bb * SEQ + r) * DMODEL + h * HD + c);
                *p = make_float2(oacc[mf][nf][rr * 2 + 0] * inv,
                                 oacc[mf][nf][rr * 2 + 1] * inv);
            }
        }
    }
}

// ---------------------------------------------------------------------------
extern "C" void kernel_launch(void* const* d_in, const int* in_sizes, int n_in,
                              void* d_out, int out_size)
{
    const float* X  = (const float*)d_in[0];
    const float* Wq = (const float*)d_in[1];
    const float* Wk = (const float*)d_in[2];
    const float* Wv = (const float*)d_in[3];
    const float* Wo = (const float*)d_in[4];
    const float* bo = (const float*)d_in[5];
    float* Out = (float*)d_out;

    cudaFuncSetAttribute(mma_gemm_kernel,
                         cudaFuncAttributeMaxDynamicSharedMemorySize, GEMM_SMEM);
    cudaFuncSetAttribute(attn_mma_kernel,
                         cudaFuncAttributeMaxDynamicSharedMemorySize, ATT_SMEM);

    float *x32_p, *ctx_p, *wt_p, *wot_p;
    cudaGetSymbolAddress((void**)&x32_p, g_x32);
    cudaGetSymbolAddress((void**)&ctx_p, g_ctx);
    cudaGetSymbolAddress((void**)&wt_p, g_wt);
    cudaGetSymbolAddress((void**)&wot_p, g_wot);

    conv_x_kernel<<<(MTOT * DMODEL / 4 + 255) / 256, 256>>>(X, x32_p);
    dim3 wgrid(DMODEL / 32, DMODEL / 32, 4);
    conv_w_kernel<<<wgrid, 256>>>(Wq, Wk, Wv, Wo);

    // fused QKV projection: [8192 x 2304] = X @ Wqkv^T (tf32)
    dim3 g1(3 * DMODEL / 128, MTOT / 128);
    mma_gemm_kernel<<<g1, 256, GEMM_SMEM>>>(x32_p, wt_p, nullptr, nullptr, 0);

    dim3 g2(SEQ / 64, BATCH * NHEADS);
    attn_mma_kernel<<<g2, 128, ATT_SMEM>>>();

    // output projection: [8192 x 768] = ctx @ Wo^T + bo (tf32)
    dim3 g3(DMODEL / 128, MTOT / 128);
    mma_gemm_kernel<<<g3, 256, GEMM_SMEM>>>(ctx_p, wot_p, bo, Out, 1);
}

// round 14
// speedup vs baseline: 1.4897x; 1.0198x over previous
#include <cuda_runtime.h>
#include <cuda_bf16.h>
#include <math.h>
#include <stdint.h>

#define NHEADS 12
#define HD 64
#define DMODEL 768
#define BATCH 4
#define SEQ 2048
#define MTOT (BATCH * SEQ)
#define KGEMM DMODEL            // 768 (direct tf32, no split)

// ---------------- device scratch (allocation-free rule) ----------------
__device__ float g_q[(size_t)BATCH * NHEADS * SEQ * HD];   // [b,h,n,d] (pre-scaled, tf32)
__device__ float g_k[(size_t)BATCH * NHEADS * SEQ * HD];   // [b,h,n,d] (tf32)
__device__ float g_v[(size_t)BATCH * NHEADS * SEQ * HD];   // [b,h,d,n] TRANSPOSED (tf32)
__device__ float g_x32[(size_t)MTOT * DMODEL];             // tf32-rounded X
__device__ float g_ctx[(size_t)MTOT * DMODEL];             // ctx (f32)
__device__ float g_wt[(size_t)(3 * DMODEL) * DMODEL];      // Wqkv^T [2304][768] tf32
__device__ float g_wot[(size_t)DMODEL * DMODEL];           // Wo^T   [768][768]  tf32

// ---------------- PTX helpers ----------------
__device__ __forceinline__ uint32_t smem_u32(const void* p) {
    uint32_t a;
    asm("{ .reg .u64 t; cvta.to.shared.u64 t, %1; cvt.u32.u64 %0, t; }"
        : "=r"(a) : "l"(p));
    return a;
}
#define CPA16(dst, src) \
    asm volatile("cp.async.cg.shared.global [%0], [%1], 16;" :: "r"(dst), "l"(src))
#define CPA_COMMIT() asm volatile("cp.async.commit_group;" ::: "memory")

__device__ __forceinline__ void ldsm4(uint32_t* r, uint32_t addr) {
    asm volatile("ldmatrix.sync.aligned.m8n8.x4.shared.b16 {%0,%1,%2,%3}, [%4];"
                 : "=r"(r[0]), "=r"(r[1]), "=r"(r[2]), "=r"(r[3]) : "r"(addr));
}
__device__ __forceinline__ void mma_tf32(float* d, const uint32_t* a,
                                         const uint32_t* b) {
    asm volatile(
        "mma.sync.aligned.m16n8k8.row.col.f32.tf32.tf32.f32 "
        "{%0,%1,%2,%3}, {%4,%5,%6,%7}, {%8,%9}, {%0,%1,%2,%3};"
        : "+f"(d[0]), "+f"(d[1]), "+f"(d[2]), "+f"(d[3])
        : "r"(a[0]), "r"(a[1]), "r"(a[2]), "r"(a[3]), "r"(b[0]), "r"(b[1]));
}
// round-to-nearest tf32. EXPENSIVE — prep kernels / epilogues ONLY.
__device__ __forceinline__ float tf32r(float x) {
    float y;
    asm("cvt.rna.tf32.f32 %0, %1;" : "=f"(y) : "f"(x));
    return y;
}
// 256B-row swizzle (attention tiles)
__device__ __forceinline__ uint32_t swz256(int row, int seg) {
    return (uint32_t)(row * 256 + (((seg ^ row) & 15) << 4) + ((seg & ~15) << 4));
}
// 128B-row swizzle (GEMM tiles)
__device__ __forceinline__ uint32_t swz128(int row, int seg) {
    return (uint32_t)(row * 128 + (((seg ^ row) & 7) << 4));
}

// ---------------- conversions ----------------
__global__ __launch_bounds__(256) void conv_x_kernel(
    const float* __restrict__ src, float* __restrict__ dst)
{
    int idx = blockIdx.x * 256 + threadIdx.x;
    if (idx >= MTOT * DMODEL / 4) return;
    float4 v = ((const float4*)src)[idx];
    v.x = tf32r(v.x); v.y = tf32r(v.y); v.z = tf32r(v.z); v.w = tf32r(v.w);
    ((float4*)dst)[idx] = v;
}

__global__ __launch_bounds__(256) void conv_w_kernel(
    const float* __restrict__ Wq, const float* __restrict__ Wk,
    const float* __restrict__ Wv, const float* __restrict__ Wo)
{
    const int z = blockIdx.z;
    const float* W = (z == 0) ? Wq : (z == 1) ? Wk : (z == 2) ? Wv : Wo;
    float* dst = (z == 3) ? g_wot : g_wt;
    const int nofs = (z == 3) ? 0 : z * DMODEL;

    __shared__ float t[32][33];
    int tx = threadIdx.x & 31, ty = threadIdx.x >> 5;
    int k0 = blockIdx.y * 32, n0 = blockIdx.x * 32;
#pragma unroll
    for (int yy = ty; yy < 32; yy += 8)
        t[yy][tx] = W[(size_t)(k0 + yy) * DMODEL + n0 + tx];
    __syncthreads();
#pragma unroll
    for (int yy = ty; yy < 32; yy += 8) {
        int n = n0 + yy, k = k0 + tx;
        dst[(size_t)(nofs + n) * KGEMM + k] = tf32r(t[tx][yy]);
    }
}

// ---------------- tf32 mma.sync GEMM (k-chunk 32, 64KB smem) ----------------
// Deep-interleaved mma order: same-accumulator writes >= 8 apart.
#define NKCH (KGEMM / 32)       // 24
#define GEMM_SMEM (2 * 32768)

__global__ __launch_bounds__(256) void mma_gemm_kernel(
    const float* __restrict__ A,
    const float* __restrict__ B,
    const float* __restrict__ bias,
    float* __restrict__ OutF, int mode)
{
    extern __shared__ char smem[];
    const uint32_t sb = smem_u32(smem);
    const int tid = threadIdx.x, wid = tid >> 5, lid = tid & 31;
    const int row0 = blockIdx.y * 128, col0 = blockIdx.x * 128;
    const int m0 = (wid & 3) * 32, n0 = (wid >> 2) * 64;

    const float* Ab = A + (size_t)row0 * KGEMM;
    const float* Bb = B + (size_t)col0 * KGEMM;

    float acc[2][8][4];
#pragma unroll
    for (int mf = 0; mf < 2; mf++)
#pragma unroll
        for (int nf = 0; nf < 8; nf++)
#pragma unroll
            for (int e = 0; e < 4; e++) acc[mf][nf][e] = 0.f;

    auto load_chunk = [&](int i, int bf) {
        const uint32_t bA = sb + bf * 32768;
        const uint32_t bB = bA + 16384;
        const int kofs = i * 32;
#pragma unroll
        for (int c = 0; c < 4; c++) {
            const int idx = tid + c * 256, row = idx >> 3, sg = idx & 7;
            const uint32_t sw = swz128(row, sg);
            CPA16(bA + sw, Ab + (size_t)row * KGEMM + kofs + sg * 4);
            CPA16(bB + sw, Bb + (size_t)row * KGEMM + kofs + sg * 4);
        }
        CPA_COMMIT();
    };

    const int asoff = lid >> 4;
    const int arow = lid & 15;
    const int brow = lid & 7, bsoff = lid >> 3;

    load_chunk(0, 0);
    for (int i = 0; i < NKCH; i++) {
        if (i + 1 < NKCH) {
            load_chunk(i + 1, (i + 1) & 1);
            asm volatile("cp.async.wait_group 1;" ::: "memory");
        } else {
            asm volatile("cp.async.wait_group 0;" ::: "memory");
        }
        __syncthreads();

        const uint32_t bufA = sb + (i & 1) * 32768;
        const uint32_t bufB = bufA + 16384;
#pragma unroll
        for (int ks = 0; ks < 2; ks++) {
            uint32_t a[2][2][4];
#pragma unroll
            for (int mf = 0; mf < 2; mf++) {
                const int rA = m0 + mf * 16 + arow;
                ldsm4(a[mf][0], bufA + swz128(rA, ks * 4 + asoff));
                ldsm4(a[mf][1], bufA + swz128(rA, ks * 4 + 2 + asoff));
            }
            // two groups of 4 nf: batch B ldsm, then h-outer interleaved mma
#pragma unroll
            for (int grp = 0; grp < 2; grp++) {
                uint32_t b4[4][4];
#pragma unroll
                for (int j = 0; j < 4; j++)
                    ldsm4(b4[j], bufB + swz128(n0 + (grp * 4 + j) * 8 + brow,
                                               ks * 4 + bsoff));
#pragma unroll
                for (int h = 0; h < 2; h++)
#pragma unroll
                    for (int j = 0; j < 4; j++)
#pragma unroll
                        for (int mf = 0; mf < 2; mf++)
                            mma_tf32(acc[mf][grp * 4 + j], a[mf][h],
                                     &b4[j][h * 2]);
            }
        }
        __syncthreads();
    }

    const int g = lid >> 2, tig = lid & 3;
#pragma unroll
    for (int mf = 0; mf < 2; mf++) {
#pragma unroll
        for (int nf = 0; nf < 8; nf++) {
            const int c = col0 + n0 + nf * 8 + tig * 2;
#pragma unroll
            for (int rr = 0; rr < 2; rr++) {
                const int r = row0 + m0 + mf * 16 + g + rr * 8;
                const float v0 = acc[mf][nf][rr * 2 + 0];
                const float v1 = acc[mf][nf][rr * 2 + 1];
                if (mode == 0) {
                    const int w = c / DMODEL;
                    const int rem = c - w * DMODEL;
                    const int h = rem >> 6, d = rem & 63;
                    const int bb = r >> 11, n = r & (SEQ - 1);
                    if (w == 0) {
                        float2* p = (float2*)(g_q +
                            ((size_t)(bb * NHEADS + h) * SEQ + n) * HD + d);
                        *p = make_float2(tf32r(v0 * 0.125f), tf32r(v1 * 0.125f));
                    } else if (w == 1) {
                        float2* p = (float2*)(g_k +
                            ((size_t)(bb * NHEADS + h) * SEQ + n) * HD + d);
                        *p = make_float2(tf32r(v0), tf32r(v1));
                    } else {
                        float* p = g_v +
                            ((size_t)(bb * NHEADS + h) * HD + d) * SEQ + n;
                        p[0] = tf32r(v0);
                        p[SEQ] = tf32r(v1);
                    }
                } else {
                    float2* p = (float2*)(OutF + (size_t)r * DMODEL + c);
                    *p = make_float2(v0 + bias[c], v1 + bias[c + 1]);
                }
            }
        }
    }
}

// ---------------------------------------------------------------------------
// Tensor-core flash attention (tf32 mma.sync, causal, no running max).
// R13 structure; S and PV phases re-ordered for accumulator-RAW distance 8
// (identical per-accumulator arithmetic order -> bit-exact results).
// ---------------------------------------------------------------------------
#define ATT_SMEM (98304 + 512)

__global__ __launch_bounds__(128) void attn_mma_kernel()
{
    extern __shared__ char smc[];
    const uint32_t sb = smem_u32(smc);
    const uint32_t Qs = sb;              // [64][64] f32 swizzled  16KB
    const uint32_t Kb = sb + 16384;      // 2 x [64][64]           32KB
    const uint32_t Vb = sb + 49152;      // 2 x [64][64] (Vt)      32KB
    const uint32_t Pb = sb + 81920;      // [64][64]               16KB
    float* larr = (float*)(smc + 98304); // [2][64] l partials

    const int tid = threadIdx.x, w = tid >> 5, lid = tid & 31;
    const int g = lid >> 2, tig = lid & 3;
    const int rq = (w & 1) * 32;
    const int ck = (w >> 1) * 32;
    const int qt = (int)gridDim.x - 1 - (int)blockIdx.x;
    const int bh = blockIdx.y;
    const int q0 = qt * 64;
    const int nk = qt + 1;

    const float* qb = g_q + (size_t)bh * SEQ * HD;
    const float* kb = g_k + (size_t)bh * SEQ * HD;
    const float* vtb = g_v + (size_t)bh * HD * SEQ;

    // ---- Q tile ----
#pragma unroll
    for (int c = 0; c < 8; c++) {
        const int idx = tid + c * 128, row = idx >> 4, seg = idx & 15;
        CPA16(Qs + swz256(row, seg), qb + (size_t)(q0 + row) * HD + seg * 4);
    }
    auto load_kv = [&](int i, int bf) {
        const int k0 = i * 64;
        const uint32_t kd = Kb + bf * 16384, vd = Vb + bf * 16384;
#pragma unroll
        for (int c = 0; c < 8; c++) {
            const int idx = tid + c * 128, row = idx >> 4, seg = idx & 15;
            const uint32_t sw = swz256(row, seg);
            CPA16(kd + sw, kb + (size_t)(k0 + row) * HD + seg * 4);
            CPA16(vd + sw, vtb + (size_t)row * SEQ + k0 + seg * 4);
        }
        CPA_COMMIT();
    };
    load_kv(0, 0);
    if (nk > 1) load_kv(1, 1);
    if (nk > 1) asm volatile("cp.async.wait_group 1;" ::: "memory");
    else        asm volatile("cp.async.wait_group 0;" ::: "memory");
    __syncthreads();

    // ---- Q fragments ----
    const int asoff = lid >> 4;
    uint32_t qf[2][8][4];
#pragma unroll
    for (int mf = 0; mf < 2; mf++) {
        const int rowQ = rq + mf * 16 + (lid & 15);
#pragma unroll
        for (int kk = 0; kk < 8; kk++)
            ldsm4(qf[mf][kk], Qs + swz256(rowQ, kk * 2 + asoff));
    }

    const int brow = lid & 7, bsoff = lid >> 3;

    float oacc[2][4][4];
#pragma unroll
    for (int mf = 0; mf < 2; mf++)
#pragma unroll
        for (int nf = 0; nf < 4; nf++)
#pragma unroll
            for (int e = 0; e < 4; e++) oacc[mf][nf][e] = 0.f;
    float lsum[2][2] = {{0.f, 0.f}, {0.f, 0.f}};

    for (int i = 0; i < nk; i++) {
        const uint32_t Kc = Kb + (i & 1) * 16384;
        const uint32_t Vc = Vb + (i & 1) * 16384;

        // ---- S = Q K^T : k2-outer, batched K ldsm, h-outer mma ----
        float sacc[2][4][4];
#pragma unroll
        for (int mf = 0; mf < 2; mf++)
#pragma unroll
            for (int nf = 0; nf < 4; nf++)
#pragma unroll
                for (int e = 0; e < 4; e++) sacc[mf][nf][e] = 0.f;
#pragma unroll
        for (int k2 = 0; k2 < 4; k2++) {
            uint32_t b4[4][4];
#pragma unroll
            for (int nf = 0; nf < 4; nf++)
                ldsm4(b4[nf], Kc + swz256(ck + nf * 8 + brow,
                                          k2 * 4 + bsoff));
#pragma unroll
            for (int h = 0; h < 2; h++)
#pragma unroll
                for (int nf = 0; nf < 4; nf++)
#pragma unroll
                    for (int mf = 0; mf < 2; mf++)
                        mma_tf32(sacc[mf][nf], qf[mf][2 * k2 + h],
                                 &b4[nf][h * 2]);
        }

        // ---- causal mask (diagonal tile only) ----
        const int k0 = i * 64;
        if (i == qt) {
#pragma unroll
            for (int mf = 0; mf < 2; mf++) {
                const int rA = q0 + rq + mf * 16 + g;
                const int rB = rA + 8;
#pragma unroll
                for (int nf = 0; nf < 4; nf++) {
                    const int c0 = k0 + ck + nf * 8 + 2 * tig;
                    if (c0 > rA) sacc[mf][nf][0] = -INFINITY;
                    if (c0 + 1 > rA) sacc[mf][nf][1] = -INFINITY;
                    if (c0 > rB) sacc[mf][nf][2] = -INFINITY;
                    if (c0 + 1 > rB) sacc[mf][nf][3] = -INFINITY;
                }
            }
        }

        // ---- P = exp(S), accumulate l, store quadrant to shared P ----
#pragma unroll
        for (int mf = 0; mf < 2; mf++) {
            const int prowA = rq + mf * 16 + g;
            const int prowB = prowA + 8;
#pragma unroll
            for (int nf = 0; nf < 4; nf++) {
                const float p0 = __expf(sacc[mf][nf][0]);
                const float p1 = __expf(sacc[mf][nf][1]);
                const float p2 = __expf(sacc[mf][nf][2]);
                const float p3 = __expf(sacc[mf][nf][3]);
                lsum[mf][0] += p0 + p1;
                lsum[mf][1] += p2 + p3;
                const int col = ck + nf * 8 + 2 * tig;
                const int segp = col >> 2, off = (col & 3) * 4;
                asm volatile("st.shared.v2.f32 [%0], {%1,%2};"
                             :: "r"(Pb + swz256(prowA, segp) + off),
                                "f"(p0), "f"(p1) : "memory");
                asm volatile("st.shared.v2.f32 [%0], {%1,%2};"
                             :: "r"(Pb + swz256(prowB, segp) + off),
                                "f"(p2), "f"(p3) : "memory");
            }
        }
        __syncthreads();   // all warps' P quadrants visible

        // ---- O += P V : batched ldsm, h-outer mma ----
#pragma unroll
        for (int k2 = 0; k2 < 4; k2++) {
            uint32_t pa[2][2][4];
#pragma unroll
            for (int mf = 0; mf < 2; mf++) {
                const int prow = rq + mf * 16 + (lid & 15);
                ldsm4(pa[mf][0], Pb + swz256(prow, (2 * k2) * 2 + asoff));
                ldsm4(pa[mf][1], Pb + swz256(prow, (2 * k2 + 1) * 2 + asoff));
            }
            uint32_t vb4[4][4];
#pragma unroll
            for (int nf = 0; nf < 4; nf++)
                ldsm4(vb4[nf], Vc + swz256(ck + nf * 8 + brow,
                                           k2 * 4 + bsoff));
#pragma unroll
            for (int h = 0; h < 2; h++)
#pragma unroll
                for (int nf = 0; nf < 4; nf++)
#pragma unroll
                    for (int mf = 0; mf < 2; mf++)
                        mma_tf32(oacc[mf][nf], pa[mf][h], &vb4[nf][h * 2]);
        }

        __syncthreads();                 // PV reads done (P + K/V bufs free)
        if (i + 2 < nk) load_kv(i + 2, i & 1);
        if (i + 1 < nk) {
            if (i + 2 < nk)
                asm volatile("cp.async.wait_group 1;" ::: "memory");
            else
                asm volatile("cp.async.wait_group 0;" ::: "memory");
            __syncthreads();
        }
    }

    // ---- l: quad-reduce then cross-warp combine via smem ----
#pragma unroll
    for (int mf = 0; mf < 2; mf++)
#pragma unroll
        for (int rr = 0; rr < 2; rr++) {
            lsum[mf][rr] += __shfl_xor_sync(0xffffffff, lsum[mf][rr], 1);
            lsum[mf][rr] += __shfl_xor_sync(0xffffffff, lsum[mf][rr], 2);
        }
    if (tig == 0) {
#pragma unroll
        for (int mf = 0; mf < 2; mf++)
#pragma unroll
            for (int rr = 0; rr < 2; rr++)
                larr[(w >> 1) * 64 + rq + mf * 16 + g + rr * 8] = lsum[mf][rr];
    }
    __syncthreads();

    // ---- epilogue: normalize + write plain f32 ctx ----
    const int bb = bh / NHEADS, h = bh - bb * NHEADS;
#pragma unroll
    for (int mf = 0; mf < 2; mf++) {
#pragma unroll
        for (int rr = 0; rr < 2; rr++) {
            const int rl = rq + mf * 16 + g + rr * 8;
            const float inv = 1.f / (larr[rl] + larr[64 + rl]);
            const int r = q0 + rl;
#pragma unroll
            for (int nf = 0; nf < 4; nf++) {
                const int c = ck + nf * 8 + 2 * tig;
                float2* p = (float2*)(g_ctx +
                    (size_t)(bb * SEQ + r) * DMODEL + h * HD + c);
                *p = make_float2(oacc[mf][nf][rr * 2 + 0] * inv,
                                 oacc[mf][nf][rr * 2 + 1] * inv);
            }
        }
    }
}

// ---------------------------------------------------------------------------
extern "C" void kernel_launch(void* const* d_in, const int* in_sizes, int n_in,
                              void* d_out, int out_size)
{
    const float* X  = (const float*)d_in[0];
    const float* Wq = (const float*)d_in[1];
    const float* Wk = (const float*)d_in[2];
    const float* Wv = (const float*)d_in[3];
    const float* Wo = (const float*)d_in[4];
    const float* bo = (const float*)d_in[5];
    float* Out = (float*)d_out;

    cudaFuncSetAttribute(mma_gemm_kernel,
                         cudaFuncAttributeMaxDynamicSharedMemorySize, GEMM_SMEM);
    cudaFuncSetAttribute(attn_mma_kernel,
                         cudaFuncAttributeMaxDynamicSharedMemorySize, ATT_SMEM);

    float *x32_p, *ctx_p, *wt_p, *wot_p;
    cudaGetSymbolAddress((void**)&x32_p, g_x32);
    cudaGetSymbolAddress((void**)&ctx_p, g_ctx);
    cudaGetSymbolAddress((void**)&wt_p, g_wt);
    cudaGetSymbolAddress((void**)&wot_p, g_wot);

    conv_x_kernel<<<(MTOT * DMODEL / 4 + 255) / 256, 256>>>(X, x32_p);
    dim3 wgrid(DMODEL / 32, DMODEL / 32, 4);
    conv_w_kernel<<<wgrid, 256>>>(Wq, Wk, Wv, Wo);

    // fused QKV projection: [8192 x 2304] = X @ Wqkv^T (tf32)
    dim3 g1(3 * DMODEL / 128, MTOT / 128);
    mma_gemm_kernel<<<g1, 256, GEMM_SMEM>>>(x32_p, wt_p, nullptr, nullptr, 0);

    dim3 g2(SEQ / 64, BATCH * NHEADS);
    attn_mma_kernel<<<g2, 128, ATT_SMEM>>>();

    // output projection: [8192 x 768] = ctx @ Wo^T + bo (tf32)
    dim3 g3(DMODEL / 128, MTOT / 128);
    mma_gemm_kernel<<<g3, 256, GEMM_SMEM>>>(ctx_p, wot_p, bo, Out, 1);
}

// round 15
// speedup vs baseline: 3.0069x; 2.0185x over previous
#include <cuda_runtime.h>
#include <cuda_fp16.h>
#include <math.h>
#include <stdint.h>

#define NHEADS 12
#define HD 64
#define DMODEL 768
#define BATCH 4
#define SEQ 2048
#define MTOT (BATCH * SEQ)
#define KGEMM DMODEL

// ---------------- device scratch (allocation-free rule) ----------------
__device__ __half g_q[(size_t)BATCH * NHEADS * SEQ * HD];   // [b,h,n,d] pre-scaled
__device__ __half g_k[(size_t)BATCH * NHEADS * SEQ * HD];   // [b,h,n,d]
__device__ __half g_v[(size_t)BATCH * NHEADS * SEQ * HD];   // [b,h,d,n] TRANSPOSED
__device__ __half g_xc[(size_t)MTOT * DMODEL];              // fp16 X
__device__ __half g_cc[(size_t)MTOT * DMODEL];              // fp16 ctx
__device__ __half g_wt[(size_t)(3 * DMODEL) * DMODEL];      // Wqkv^T [2304][768]
__device__ __half g_wot[(size_t)DMODEL * DMODEL];           // Wo^T   [768][768]

// ---------------- PTX helpers ----------------
__device__ __forceinline__ uint32_t smem_u32(const void* p) {
    uint32_t a;
    asm("{ .reg .u64 t; cvta.to.shared.u64 t, %1; cvt.u32.u64 %0, t; }"
        : "=r"(a) : "l"(p));
    return a;
}
#define CPA16(dst, src) \
    asm volatile("cp.async.cg.shared.global [%0], [%1], 16;" :: "r"(dst), "l"(src))
#define CPA_COMMIT() asm volatile("cp.async.commit_group;" ::: "memory")

__device__ __forceinline__ void ldsm4(uint32_t* r, uint32_t addr) {
    asm volatile("ldmatrix.sync.aligned.m8n8.x4.shared.b16 {%0,%1,%2,%3}, [%4];"
                 : "=r"(r[0]), "=r"(r[1]), "=r"(r[2]), "=r"(r[3]) : "r"(addr));
}
__device__ __forceinline__ void mma_f16(float* d, const uint32_t* a,
                                        const uint32_t* b) {
    asm volatile(
        "mma.sync.aligned.m16n8k16.row.col.f32.f16.f16.f32 "
        "{%0,%1,%2,%3}, {%4,%5,%6,%7}, {%8,%9}, {%0,%1,%2,%3};"
        : "+f"(d[0]), "+f"(d[1]), "+f"(d[2]), "+f"(d[3])
        : "r"(a[0]), "r"(a[1]), "r"(a[2]), "r"(a[3]), "r"(b[0]), "r"(b[1]));
}
// pack two f32 into f16x2 {lo=a, hi=b}
__device__ __forceinline__ uint32_t pack_h2(float a, float b) {
    uint32_t r;
    asm("cvt.rn.f16x2.f32 %0, %1, %2;" : "=r"(r) : "f"(b), "f"(a));
    return r;
}
// 128B-row swizzle: 16B seg XOR low 3 row bits
__device__ __forceinline__ uint32_t swz128(int row, int seg) {
    return (uint32_t)(row * 128 + (((seg ^ row) & 7) << 4));
}

// ---------------- conversions ----------------
__global__ __launch_bounds__(256) void conv_x_kernel(
    const float* __restrict__ src, __half* __restrict__ dst)
{
    int idx = blockIdx.x * 256 + threadIdx.x;
    if (idx >= MTOT * DMODEL / 2) return;
    float2 v = ((const float2*)src)[idx];
    ((__half2*)dst)[idx] = __float22half2_rn(v);
}

// Transpose W[k][n] -> Wt[n][k] fp16. z selects Wq/Wk/Wv/Wo.
__global__ __launch_bounds__(256) void conv_w_kernel(
    const float* __restrict__ Wq, const float* __restrict__ Wk,
    const float* __restrict__ Wv, const float* __restrict__ Wo)
{
    const int z = blockIdx.z;
    const float* W = (z == 0) ? Wq : (z == 1) ? Wk : (z == 2) ? Wv : Wo;
    __half* dst = (z == 3) ? g_wot : g_wt;
    const int nofs = (z == 3) ? 0 : z * DMODEL;

    __shared__ float t[32][33];
    int tx = threadIdx.x & 31, ty = threadIdx.x >> 5;
    int k0 = blockIdx.y * 32, n0 = blockIdx.x * 32;
#pragma unroll
    for (int yy = ty; yy < 32; yy += 8)
        t[yy][tx] = W[(size_t)(k0 + yy) * DMODEL + n0 + tx];
    __syncthreads();
#pragma unroll
    for (int yy = ty; yy < 32; yy += 8) {
        int n = n0 + yy, k = k0 + tx;
        dst[(size_t)(nofs + n) * KGEMM + k] = __float2half_rn(t[tx][yy]);
    }
}

// ---------------- fp16 mma.sync GEMM (R4 structure, K=768 single pass) -----
// C[128x128] = A[row0:+128,:768] x B[col0:+128,:768]^T, k-chunk 64, 2-stage.
#define NKCH (KGEMM / 64)       // 12
#define GEMM_SMEM (2 * 32768)

__global__ __launch_bounds__(256) void mma_gemm_kernel(
    const __half* __restrict__ A,
    const __half* __restrict__ B,
    const float* __restrict__ bias,
    float* __restrict__ OutF, int mode)
{
    extern __shared__ char smem[];
    const uint32_t sb = smem_u32(smem);
    const int tid = threadIdx.x, wid = tid >> 5, lid = tid & 31;
    const int row0 = blockIdx.y * 128, col0 = blockIdx.x * 128;
    const int m0 = (wid & 3) * 32, n0 = (wid >> 2) * 64;

    const int seg = tid & 7;
    const int rowq = tid >> 3;
    const __half* Ab = A + (size_t)row0 * KGEMM;
    const __half* Bb = B + (size_t)col0 * KGEMM;

    float acc[2][8][4];
#pragma unroll
    for (int mf = 0; mf < 2; mf++)
#pragma unroll
        for (int nf = 0; nf < 8; nf++)
#pragma unroll
            for (int e = 0; e < 4; e++) acc[mf][nf][e] = 0.f;

    auto load_chunk = [&](int i, int bf) {
        const uint32_t bA = sb + bf * 32768;
        const uint32_t bB = bA + 16384;
        const size_t kofs = (size_t)i * 64 + seg * 8;
#pragma unroll
        for (int gg = 0; gg < 4; gg++) {
            const int r = rowq + gg * 32;
            const uint32_t sw = swz128(r, seg);
            CPA16(bA + sw, Ab + (size_t)r * KGEMM + kofs);
            CPA16(bB + sw, Bb + (size_t)r * KGEMM + kofs);
        }
        CPA_COMMIT();
    };

    const int rowA = lid & 15;
    const int aseg = lid >> 4;                 // 0/1 (16B col half)
    const int rowB = ((lid >> 4) << 3) + (lid & 7);
    const int bseg = (lid >> 3) & 1;

    load_chunk(0, 0);
    for (int i = 0; i < NKCH; i++) {
        if (i + 1 < NKCH) {
            load_chunk(i + 1, (i + 1) & 1);
            asm volatile("cp.async.wait_group 1;" ::: "memory");
        } else {
            asm volatile("cp.async.wait_group 0;" ::: "memory");
        }
        __syncthreads();

        const uint32_t bufA = sb + (i & 1) * 32768;
        const uint32_t bufB = bufA + 16384;
#pragma unroll
        for (int ks = 0; ks < 4; ks++) {
            uint32_t a[2][4], b[4][4];
#pragma unroll
            for (int mf = 0; mf < 2; mf++)
                ldsm4(a[mf], bufA + swz128(m0 + mf * 16 + rowA,
                                           ks * 2 + aseg));
#pragma unroll
            for (int bj = 0; bj < 4; bj++)
                ldsm4(b[bj], bufB + swz128(n0 + bj * 16 + rowB,
                                           ks * 2 + bseg));
#pragma unroll
            for (int mf = 0; mf < 2; mf++)
#pragma unroll
                for (int nf = 0; nf < 8; nf++)
                    mma_f16(acc[mf][nf], a[mf], &b[nf >> 1][(nf & 1) * 2]);
        }
        __syncthreads();
    }

    const int g = lid >> 2, tig = lid & 3;
#pragma unroll
    for (int mf = 0; mf < 2; mf++) {
#pragma unroll
        for (int nf = 0; nf < 8; nf++) {
            const int c = col0 + n0 + nf * 8 + tig * 2;
#pragma unroll
            for (int rr = 0; rr < 2; rr++) {
                const int r = row0 + m0 + mf * 16 + g + rr * 8;
                const float v0 = acc[mf][nf][rr * 2 + 0];
                const float v1 = acc[mf][nf][rr * 2 + 1];
                if (mode == 0) {
                    const int w = c / DMODEL;
                    const int rem = c - w * DMODEL;
                    const int h = rem >> 6, d = rem & 63;
                    const int bb = r >> 11, n = r & (SEQ - 1);
                    if (w == 0) {        // Q: pre-scale 1/8
                        __half2* p = (__half2*)(g_q +
                            ((size_t)(bb * NHEADS + h) * SEQ + n) * HD + d);
                        *p = __float22half2_rn(
                            make_float2(v0 * 0.125f, v1 * 0.125f));
                    } else if (w == 1) { // K
                        __half2* p = (__half2*)(g_k +
                            ((size_t)(bb * NHEADS + h) * SEQ + n) * HD + d);
                        *p = __float22half2_rn(make_float2(v0, v1));
                    } else {             // V transposed [b,h,d,n]
                        __half* p = g_v +
                            ((size_t)(bb * NHEADS + h) * HD + d) * SEQ + n;
                        p[0] = __float2half_rn(v0);
                        p[SEQ] = __float2half_rn(v1);
                    }
                } else {
                    float2* p = (float2*)(OutF + (size_t)r * DMODEL + c);
                    *p = make_float2(v0 + bias[c], v1 + bias[c + 1]);
                }
            }
        }
    }
}

// ---------------------------------------------------------------------------
// fp16 flash attention (mma.sync m16n8k16, causal, no running max).
// Quadrant mapping (R13 structure), fp16 tiles (128B rows), K/V double-buffered.
// Smem 48.5KB + __launch_bounds__(128,3) -> 3 CTAs / 12 warps per SM.
// ---------------------------------------------------------------------------
#define ATT_SMEM (8192 + 16384 + 16384 + 8192 + 512)

__global__ __launch_bounds__(128, 3) void attn_mma_kernel()
{
    extern __shared__ char smc[];
    const uint32_t sb = smem_u32(smc);
    const uint32_t Qs = sb;              // [64][64] fp16        8KB
    const uint32_t Kb = sb + 8192;       // 2 x [64][64] fp16   16KB
    const uint32_t Vb = sb + 24576;      // 2 x [64][64] (Vt)   16KB
    const uint32_t Pb = sb + 40960;      // [64][64] fp16        8KB
    float* larr = (float*)(smc + 49152); // [2][64] l partials

    const int tid = threadIdx.x, w = tid >> 5, lid = tid & 31;
    const int g = lid >> 2, tig = lid & 3;
    const int rq = (w & 1) * 32;         // q-row quadrant base
    const int ck = (w >> 1) * 32;        // k / d-col quadrant base
    const int qt = (int)gridDim.x - 1 - (int)blockIdx.x;   // heavy first
    const int bh = blockIdx.y;
    const int q0 = qt * 64;
    const int nk = qt + 1;

    const __half* qb = g_q + (size_t)bh * SEQ * HD;
    const __half* kb = g_k + (size_t)bh * SEQ * HD;
    const __half* vtb = g_v + (size_t)bh * HD * SEQ;   // [d][n]

    // ---- Q tile: 64 rows x 8 segs = 512 chunks over 128 threads ----
#pragma unroll
    for (int c = 0; c < 4; c++) {
        const int idx = tid + c * 128, row = idx >> 3, seg = idx & 7;
        CPA16(Qs + swz128(row, seg), qb + (size_t)(q0 + row) * HD + seg * 8);
    }
    auto load_kv = [&](int i, int bf) {
        const int k0 = i * 64;
        const uint32_t kd = Kb + bf * 8192, vd = Vb + bf * 8192;
#pragma unroll
        for (int c = 0; c < 4; c++) {
            const int idx = tid + c * 128, row = idx >> 3, seg = idx & 7;
            const uint32_t sw = swz128(row, seg);
            CPA16(kd + sw, kb + (size_t)(k0 + row) * HD + seg * 8);
            CPA16(vd + sw, vtb + (size_t)row * SEQ + k0 + seg * 8);
        }
        CPA_COMMIT();
    };
    load_kv(0, 0);
    if (nk > 1) load_kv(1, 1);
    if (nk > 1) asm volatile("cp.async.wait_group 1;" ::: "memory");
    else        asm volatile("cp.async.wait_group 0;" ::: "memory");
    __syncthreads();

    // ---- Q fragments: 2 mf x 4 k16-steps, in registers (32 regs) ----
    const int arow = lid & 15;
    const int aseg = lid >> 4;
    uint32_t qf[2][4][4];
#pragma unroll
    for (int mf = 0; mf < 2; mf++) {
        const int rowQ = rq + mf * 16 + arow;
#pragma unroll
        for (int st = 0; st < 4; st++)
            ldsm4(qf[mf][st], Qs + swz128(rowQ, st * 2 + aseg));
    }

    const int rowB = ((lid >> 4) << 3) + (lid & 7);
    const int bseg = (lid >> 3) & 1;

    float oacc[2][4][4];
#pragma unroll
    for (int mf = 0; mf < 2; mf++)
#pragma unroll
        for (int nf = 0; nf < 4; nf++)
#pragma unroll
            for (int e = 0; e < 4; e++) oacc[mf][nf][e] = 0.f;
    float lsum[2][2] = {{0.f, 0.f}, {0.f, 0.f}};

    for (int i = 0; i < nk; i++) {
        const uint32_t Kc = Kb + (i & 1) * 8192;
        const uint32_t Vc = Vb + (i & 1) * 8192;

        // ---- S quadrant = Q[rq:+32] K[ck:+32]^T ----
        float sacc[2][4][4];
#pragma unroll
        for (int mf = 0; mf < 2; mf++)
#pragma unroll
            for (int nf = 0; nf < 4; nf++)
#pragma unroll
                for (int e = 0; e < 4; e++) sacc[mf][nf][e] = 0.f;
#pragma unroll
        for (int st = 0; st < 4; st++) {
            uint32_t kb4[2][4];
#pragma unroll
            for (int j = 0; j < 2; j++)
                ldsm4(kb4[j], Kc + swz128(ck + j * 16 + rowB,
                                          st * 2 + bseg));
#pragma unroll
            for (int nf = 0; nf < 4; nf++)
#pragma unroll
                for (int mf = 0; mf < 2; mf++)
                    mma_f16(sacc[mf][nf], qf[mf][st],
                            &kb4[nf >> 1][(nf & 1) * 2]);
        }

        // ---- causal mask (diagonal tile only) ----
        const int k0 = i * 64;
        if (i == qt) {
#pragma unroll
            for (int mf = 0; mf < 2; mf++) {
                const int rA = q0 + rq + mf * 16 + g;
                const int rB = rA + 8;
#pragma unroll
                for (int nf = 0; nf < 4; nf++) {
                    const int c0 = k0 + ck + nf * 8 + 2 * tig;
                    if (c0 > rA) sacc[mf][nf][0] = -INFINITY;
                    if (c0 + 1 > rA) sacc[mf][nf][1] = -INFINITY;
                    if (c0 > rB) sacc[mf][nf][2] = -INFINITY;
                    if (c0 + 1 > rB) sacc[mf][nf][3] = -INFINITY;
                }
            }
        }

        // ---- P = exp(S), accumulate l, store fp16 quadrant to shared ----
#pragma unroll
        for (int mf = 0; mf < 2; mf++) {
            const int prowA = rq + mf * 16 + g;
            const int prowB = prowA + 8;
#pragma unroll
            for (int nf = 0; nf < 4; nf++) {
                const float p0 = __expf(sacc[mf][nf][0]);
                const float p1 = __expf(sacc[mf][nf][1]);
                const float p2 = __expf(sacc[mf][nf][2]);
                const float p3 = __expf(sacc[mf][nf][3]);
                lsum[mf][0] += p0 + p1;
                lsum[mf][1] += p2 + p3;
                const int cbyte = (ck + nf * 8 + 2 * tig) * 2;
                const int segp = cbyte >> 4, off = cbyte & 15;
                asm volatile("st.shared.b32 [%0], %1;"
                             :: "r"(Pb + swz128(prowA, segp) + off),
                                "r"(pack_h2(p0, p1)) : "memory");
                asm volatile("st.shared.b32 [%0], %1;"
                             :: "r"(Pb + swz128(prowB, segp) + off),
                                "r"(pack_h2(p2, p3)) : "memory");
            }
        }
        __syncthreads();   // all warps' P quadrants visible

        // ---- O quadrant += P[rq:+32, :] V[:, ck:+32] ----
#pragma unroll
        for (int st = 0; st < 4; st++) {
            uint32_t pa[2][4];
#pragma unroll
            for (int mf = 0; mf < 2; mf++)
                ldsm4(pa[mf], Pb + swz128(rq + mf * 16 + arow,
                                          st * 2 + aseg));
            uint32_t vb4[2][4];
#pragma unroll
            for (int j = 0; j < 2; j++)
                ldsm4(vb4[j], Vc + swz128(ck + j * 16 + rowB,
                                          st * 2 + bseg));
#pragma unroll
            for (int nf = 0; nf < 4; nf++)
#pragma unroll
                for (int mf = 0; mf < 2; mf++)
                    mma_f16(oacc[mf][nf], pa[mf],
                            &vb4[nf >> 1][(nf & 1) * 2]);
        }

        __syncthreads();                 // PV reads done (P + K/V bufs free)
        if (i + 2 < nk) load_kv(i + 2, i & 1);
        if (i + 1 < nk) {
            if (i + 2 < nk)
                asm volatile("cp.async.wait_group 1;" ::: "memory");
            else
                asm volatile("cp.async.wait_group 0;" ::: "memory");
            __syncthreads();
        }
    }

    // ---- l: quad-reduce then cross-warp combine via smem ----
#pragma unroll
    for (int mf = 0; mf < 2; mf++)
#pragma unroll
        for (int rr = 0; rr < 2; rr++) {
            lsum[mf][rr] += __shfl_xor_sync(0xffffffff, lsum[mf][rr], 1);
            lsum[mf][rr] += __shfl_xor_sync(0xffffffff, lsum[mf][rr], 2);
        }
    if (tig == 0) {
#pragma unroll
        for (int mf = 0; mf < 2; mf++)
#pragma unroll
            for (int rr = 0; rr < 2; rr++)
                larr[(w >> 1) * 64 + rq + mf * 16 + g + rr * 8] = lsum[mf][rr];
    }
    __syncthreads();

    // ---- epilogue: normalize + write fp16 ctx ----
    const int bb = bh / NHEADS, h = bh - bb * NHEADS;
#pragma unroll
    for (int mf = 0; mf < 2; mf++) {
#pragma unroll
        for (int rr = 0; rr < 2; rr++) {
            const int rl = rq + mf * 16 + g + rr * 8;
            const float inv = 1.f / (larr[rl] + larr[64 + rl]);
            const int r = q0 + rl;
#pragma unroll
            for (int nf = 0; nf < 4; nf++) {
                const int c = ck + nf * 8 + 2 * tig;
                __half2* p = (__half2*)(g_cc +
                    (size_t)(bb * SEQ + r) * DMODEL + h * HD + c);
                *p = __float22half2_rn(
                    make_float2(oacc[mf][nf][rr * 2 + 0] * inv,
                                oacc[mf][nf][rr * 2 + 1] * inv));
            }
        }
    }
}

// ---------------------------------------------------------------------------
extern "C" void kernel_launch(void* const* d_in, const int* in_sizes, int n_in,
                              void* d_out, int out_size)
{
    const float* X  = (const float*)d_in[0];
    const float* Wq = (const float*)d_in[1];
    const float* Wk = (const float*)d_in[2];
    const float* Wv = (const float*)d_in[3];
    const float* Wo = (const float*)d_in[4];
    const float* bo = (const float*)d_in[5];
    float* Out = (float*)d_out;

    cudaFuncSetAttribute(mma_gemm_kernel,
                         cudaFuncAttributeMaxDynamicSharedMemorySize, GEMM_SMEM);
    cudaFuncSetAttribute(attn_mma_kernel,
                         cudaFuncAttributeMaxDynamicSharedMemorySize, ATT_SMEM);

    __half *xc_p, *cc_p, *wt_p, *wot_p;
    cudaGetSymbolAddress((void**)&xc_p, g_xc);
    cudaGetSymbolAddress((void**)&cc_p, g_cc);
    cudaGetSymbolAddress((void**)&wt_p, g_wt);
    cudaGetSymbolAddress((void**)&wot_p, g_wot);

    conv_x_kernel<<<(MTOT * DMODEL / 2 + 255) / 256, 256>>>(X, xc_p);
    dim3 wgrid(DMODEL / 32, DMODEL / 32, 4);
    conv_w_kernel<<<wgrid, 256>>>(Wq, Wk, Wv, Wo);

    // fused QKV projection: [8192 x 2304] = X @ Wqkv^T (fp16, K=768)
    dim3 g1(3 * DMODEL / 128, MTOT / 128);
    mma_gemm_kernel<<<g1, 256, GEMM_SMEM>>>(xc_p, wt_p, nullptr, nullptr, 0);

    dim3 g2(SEQ / 64, BATCH * NHEADS);
    attn_mma_kernel<<<g2, 128, ATT_SMEM>>>();

    // output projection: [8192 x 768] = ctx @ Wo^T + bo (fp16)
    dim3 g3(DMODEL / 128, MTOT / 128);
    mma_gemm_kernel<<<g3, 256, GEMM_SMEM>>>(cc_p, wot_p, bo, Out, 1);
}